// round 2
// baseline (speedup 1.0000x reference)
#include <cuda_runtime.h>

// Problem constants
#define B_    4
#define Qn    256
#define Kn    1024
#define Din   256
#define H_    128
#define Vn    256

// Scratch for projections (no cudaMalloc allowed)
__device__ float d_qproj[B_ * Qn * H_];   // [b][q][h]
__device__ float d_kproj[B_ * Kn * H_];   // [b][k][h]

__device__ __forceinline__ float tanh_fast(float x) {
    float y;
    asm("tanh.approx.f32 %0, %1;" : "=f"(y) : "f"(x));
    return y;
}

// out[row][h] = dot(X[row, :], W[h, :])   (torch Linear: x @ W^T)
// grid = rows, block = 256 (8 warps). Warp w computes h = w + 8*j.
__global__ void proj_kernel(const float* __restrict__ X,
                            const float* __restrict__ W,
                            int which /*0 -> qproj, 1 -> kproj*/) {
    float* __restrict__ out = which ? d_kproj : d_qproj;
    const int row = blockIdx.x;
    __shared__ float xs[Din];
    const int tid  = threadIdx.x;
    const int warp = tid >> 5;
    const int lane = tid & 31;

    xs[tid] = X[row * Din + tid];
    __syncthreads();

    #pragma unroll
    for (int j = 0; j < H_ / 8; j++) {
        const int h = warp + 8 * j;
        const float* __restrict__ w = W + h * Din;
        float acc = 0.f;
        #pragma unroll
        for (int m = 0; m < Din / 32; m++)
            acc = fmaf(xs[lane + 32 * m], __ldg(&w[lane + 32 * m]), acc);
        #pragma unroll
        for (int off = 16; off; off >>= 1)
            acc += __shfl_xor_sync(0xffffffffu, acc, off);
        if (lane == 0) out[row * H_ + h] = acc;
    }
}

// One block per (b, q) row. 256 threads = 8 warps.
// Phase A: warp-per-key additive scores (tanh on MUFU), only k < valid_len.
// Phase B: masked softmax over shared scores.
// Phase C: out[v] = sum_k attn[k] * values[b,k,v], thread v = tid.
__global__ void attn_kernel(const float* __restrict__ values,
                            const int*   __restrict__ valid_lens,
                            const float* __restrict__ wv_g,
                            float* __restrict__ out) {
    const int b = blockIdx.x / Qn;
    const int q = blockIdx.x % Qn;

    __shared__ float qs[H_];
    __shared__ float wvs[H_];
    __shared__ float sc[Kn];
    __shared__ float red[8];

    const int tid  = threadIdx.x;
    const int warp = tid >> 5;
    const int lane = tid & 31;

    if (tid < H_) {
        qs[tid]  = d_qproj[(b * Qn + q) * H_ + tid];
        wvs[tid] = wv_g[tid];
    }
    const int valid = valid_lens[b];
    __syncthreads();

    // ---- Phase A: scores for k in [0, valid) ----
    for (int k = warp; k < valid; k += 8) {
        const float* __restrict__ kr = d_kproj + (b * Kn + k) * H_;
        float acc = 0.f;
        #pragma unroll
        for (int j = 0; j < 4; j++) {
            const int h = lane + 32 * j;
            acc = fmaf(wvs[h], tanh_fast(qs[h] + __ldg(&kr[h])), acc);
        }
        #pragma unroll
        for (int off = 16; off; off >>= 1)
            acc += __shfl_xor_sync(0xffffffffu, acc, off);
        if (lane == 0) sc[k] = acc;
    }
    __syncthreads();

    // ---- Phase B: softmax over sc[0..valid) ----
    float m = -1e30f;
    for (int k = tid; k < valid; k += 256) m = fmaxf(m, sc[k]);
    #pragma unroll
    for (int off = 16; off; off >>= 1)
        m = fmaxf(m, __shfl_xor_sync(0xffffffffu, m, off));
    if (lane == 0) red[warp] = m;
    __syncthreads();
    if (tid == 0) {
        float mm = red[0];
        #pragma unroll
        for (int i = 1; i < 8; i++) mm = fmaxf(mm, red[i]);
        red[0] = mm;
    }
    __syncthreads();
    m = red[0];
    __syncthreads();   // everyone has read red[0] before it is reused

    float s = 0.f;
    for (int k = tid; k < valid; k += 256) {
        const float e = __expf(sc[k] - m);
        sc[k] = e;
        s += e;
    }
    #pragma unroll
    for (int off = 16; off; off >>= 1)
        s += __shfl_xor_sync(0xffffffffu, s, off);
    if (lane == 0) red[warp] = s;
    __syncthreads();
    if (tid == 0) {
        float ss = 0.f;
        #pragma unroll
        for (int i = 0; i < 8; i++) ss += red[i];
        red[0] = ss;
    }
    __syncthreads();
    const float inv = 1.0f / red[0];

    // ---- Phase C: weighted sum of values. thread tid handles column v = tid ----
    const float* __restrict__ vbase = values + (size_t)b * Kn * Vn + tid;
    float acc = 0.f;
    int k = 0;
    for (; k + 8 <= valid; k += 8) {
        #pragma unroll
        for (int u = 0; u < 8; u++)
            acc = fmaf(sc[k + u], __ldg(&vbase[(size_t)(k + u) * Vn]), acc);
    }
    for (; k < valid; k++)
        acc = fmaf(sc[k], __ldg(&vbase[(size_t)k * Vn]), acc);

    out[((size_t)b * Qn + q) * Vn + tid] = acc * inv;
}

extern "C" void kernel_launch(void* const* d_in, const int* in_sizes, int n_in,
                              void* d_out, int out_size) {
    const float* queries    = (const float*)d_in[0];  // [4,256,256]
    const float* keys       = (const float*)d_in[1];  // [4,1024,256]
    const float* values     = (const float*)d_in[2];  // [4,1024,256]
    const int*   valid_lens = (const int*)  d_in[3];  // [4]
    const float* W_q        = (const float*)d_in[4];  // [128,256]
    const float* W_k        = (const float*)d_in[5];  // [128,256]
    const float* w_v        = (const float*)d_in[6];  // [128]
    float* out              = (float*)d_out;          // [4,256,256]

    proj_kernel<<<B_ * Qn, 256>>>(queries, W_q, 0);
    proj_kernel<<<B_ * Kn, 256>>>(keys,    W_k, 1);
    attn_kernel<<<B_ * Qn, 256>>>(values, valid_lens, w_v, out);
}

// round 3
// speedup vs baseline: 1.0220x; 1.0220x over previous
#include <cuda_runtime.h>

#define B_    4
#define Qn    256
#define Kn    1024
#define Din   256
#define H_    128
#define Vn    256

// Scratch (no cudaMalloc allowed)
__device__ float d_qproj[B_ * Qn * H_];          // [b*Q+q][h]
__device__ float d_kproj[B_ * Kn * H_];          // [b*K+k][h]
__device__ float d_scores[B_ * Qn * Kn];         // [b][q][k]

__device__ __forceinline__ float tanh_fast(float x) {
    float y;
    asm("tanh.approx.f32 %0, %1;" : "=f"(y) : "f"(x));
    return y;
}

// ---------------------------------------------------------------------------
// Kernel 1: fused projection GEMM.  out[row][h] = dot(X[row,:], W[h,:])
// BM=32 rows, BN=128 (=H), BK=32.  256 threads, 4x4 register tile each.
// Blocks 0..31: queries -> d_qproj.  Blocks 32..159: keys -> d_kproj.
// ---------------------------------------------------------------------------
__global__ __launch_bounds__(256) void proj_gemm(const float* __restrict__ Xq,
                                                 const float* __restrict__ Xk,
                                                 const float* __restrict__ Wq,
                                                 const float* __restrict__ Wk) {
    const int blk = blockIdx.x;
    const float* X; const float* W; float* out; int row0;
    if (blk < 32) { X = Xq; W = Wq; out = d_qproj; row0 = blk * 32; }
    else          { X = Xk; W = Wk; out = d_kproj; row0 = (blk - 32) * 32; }

    __shared__ float As[32][33];    // [kk][m], pad 33 for conflict-free STS
    __shared__ float Bs[32][128];   // [kk][h]

    const int tid = threadIdx.x;
    const int tx = tid & 31, ty = tid >> 5;
    float acc[4][4] = {};

    for (int k0 = 0; k0 < Din; k0 += 32) {
        // A tile: X[row0+r][k0+4*f4 .. +3]  (r=tid/8, f4=tid%8)
        {
            const int r = tid >> 3, f4 = tid & 7;
            float4 v = *(const float4*)&X[(row0 + r) * Din + k0 + f4 * 4];
            As[f4 * 4 + 0][r] = v.x; As[f4 * 4 + 1][r] = v.y;
            As[f4 * 4 + 2][r] = v.z; As[f4 * 4 + 3][r] = v.w;
        }
        // B tile: W[h][k0+4*f4 .. +3] -> Bs[kk][h]
        #pragma unroll
        for (int i = 0; i < 4; i++) {
            const int idx = tid + 256 * i;      // 0..1023
            const int h = idx >> 3, f4 = idx & 7;
            float4 v = *(const float4*)&W[h * Din + k0 + f4 * 4];
            Bs[f4 * 4 + 0][h] = v.x; Bs[f4 * 4 + 1][h] = v.y;
            Bs[f4 * 4 + 2][h] = v.z; Bs[f4 * 4 + 3][h] = v.w;
        }
        __syncthreads();

        #pragma unroll
        for (int kk = 0; kk < 32; kk++) {
            float a[4];
            #pragma unroll
            for (int m = 0; m < 4; m++) a[m] = As[kk][ty * 4 + m];   // broadcast
            const float4 bv = *(const float4*)&Bs[kk][tx * 4];
            const float bb[4] = {bv.x, bv.y, bv.z, bv.w};
            #pragma unroll
            for (int m = 0; m < 4; m++)
                #pragma unroll
                for (int n = 0; n < 4; n++)
                    acc[m][n] = fmaf(a[m], bb[n], acc[m][n]);
        }
        __syncthreads();
    }
    #pragma unroll
    for (int m = 0; m < 4; m++) {
        float4 v = make_float4(acc[m][0], acc[m][1], acc[m][2], acc[m][3]);
        *(float4*)&out[(row0 + ty * 4 + m) * H_ + tx * 4] = v;
    }
}

// ---------------------------------------------------------------------------
// Kernel 2: additive scores, tiled 64q x 64k per block.
// blockIdx.x = b*64 + qt*16 + kt   (qt in 0..3, kt in 0..15)
// Warp w handles k_local = w*8 + i.  Per (q,k): 4 tanh + 4 fma + shfl reduce.
// ---------------------------------------------------------------------------
__global__ __launch_bounds__(256) void score_kernel(const int* __restrict__ valid_lens,
                                                    const float* __restrict__ wv) {
    const int idx = blockIdx.x;
    const int b  = idx >> 6;
    const int qt = (idx >> 4) & 3;
    const int kt = idx & 15;
    const int q0 = qt * 64, k0 = kt * 64;
    const int valid = valid_lens[b];
    if (k0 >= valid) return;
    const int kend = min(valid - k0, 64);

    __shared__ float qs[64 * 128];
    __shared__ float scs[64][64];

    const int tid = threadIdx.x, lane = tid & 31, w = tid >> 5;

    const float* __restrict__ qp = d_qproj + (b * Qn + q0) * H_;
    for (int i = tid; i < 64 * 128 / 4; i += 256)
        ((float4*)qs)[i] = ((const float4*)qp)[i];
    const float4 wv4 = *(const float4*)&wv[lane * 4];
    __syncthreads();

    #pragma unroll 1
    for (int i = 0; i < 8; i++) {
        const int kl = w * 8 + i;
        if (kl >= kend) break;
        const int k = k0 + kl;
        const float4 kr = *(const float4*)&d_kproj[(b * Kn + k) * H_ + lane * 4];
        #pragma unroll 4
        for (int q = 0; q < 64; q++) {
            const float4 a = *(const float4*)&qs[q * 128 + lane * 4];
            float acc;
            acc = wv4.x * tanh_fast(a.x + kr.x);
            acc = fmaf(wv4.y, tanh_fast(a.y + kr.y), acc);
            acc = fmaf(wv4.z, tanh_fast(a.z + kr.z), acc);
            acc = fmaf(wv4.w, tanh_fast(a.w + kr.w), acc);
            #pragma unroll
            for (int off = 16; off; off >>= 1)
                acc += __shfl_xor_sync(0xffffffffu, acc, off);
            if (lane == 0) scs[q][kl] = acc;
        }
    }
    __syncthreads();

    // coalesced float4 store of the 64x64 tile (garbage beyond kend is never read)
    float* __restrict__ dst = d_scores + (b * Qn + q0) * Kn + k0;
    for (int i = tid; i < 64 * 16; i += 256) {
        const int q = i >> 4, f4 = i & 15;
        *(float4*)&dst[q * Kn + f4 * 4] = *(const float4*)&scs[q][f4 * 4];
    }
}

// ---------------------------------------------------------------------------
// Kernel 3: masked softmax + attn @ V.  Block = (b, 8 query rows).
// Warp w owns softmax of row q0+w; then thread tid = value column,
// 8 per-q accumulators, float4 attention broadcasts.
// ---------------------------------------------------------------------------
__global__ __launch_bounds__(256) void softmax_av(const float* __restrict__ values,
                                                  const int* __restrict__ valid_lens,
                                                  float* __restrict__ out) {
    const int b  = blockIdx.x >> 5;
    const int q0 = (blockIdx.x & 31) * 8;
    const int valid = valid_lens[b];

    __shared__ float at[8][Kn];
    __shared__ float invs[8];

    const int tid = threadIdx.x, lane = tid & 31, w = tid >> 5;

    // ---- per-warp softmax of row q0+w over k < valid ----
    const float* __restrict__ srow = d_scores + (b * Qn + q0 + w) * Kn;
    float m = -1e30f;
    for (int k = lane; k < valid; k += 32) {
        const float v = srow[k];
        at[w][k] = v;
        m = fmaxf(m, v);
    }
    #pragma unroll
    for (int off = 16; off; off >>= 1)
        m = fmaxf(m, __shfl_xor_sync(0xffffffffu, m, off));

    float s = 0.f;
    for (int k = lane; k < valid; k += 32) {
        const float e = __expf(at[w][k] - m);
        at[w][k] = e;
        s += e;
    }
    #pragma unroll
    for (int off = 16; off; off >>= 1)
        s += __shfl_xor_sync(0xffffffffu, s, off);
    if (lane == 0) invs[w] = 1.0f / s;
    __syncthreads();

    // ---- AV: thread = value column, 8 q accumulators ----
    float acc[8] = {};
    const float* __restrict__ vb = values + (size_t)b * Kn * Vn + tid;
    int k = 0;
    const int v4 = valid & ~3;
    for (; k < v4; k += 4) {
        float vv[4];
        #pragma unroll
        for (int u = 0; u < 4; u++) vv[u] = __ldg(&vb[(size_t)(k + u) * Vn]);
        #pragma unroll
        for (int qq = 0; qq < 8; qq++) {
            const float4 a = *(const float4*)&at[qq][k];
            acc[qq] = fmaf(a.x, vv[0], acc[qq]);
            acc[qq] = fmaf(a.y, vv[1], acc[qq]);
            acc[qq] = fmaf(a.z, vv[2], acc[qq]);
            acc[qq] = fmaf(a.w, vv[3], acc[qq]);
        }
    }
    for (; k < valid; k++) {
        const float vv = __ldg(&vb[(size_t)k * Vn]);
        #pragma unroll
        for (int qq = 0; qq < 8; qq++)
            acc[qq] = fmaf(at[qq][k], vv, acc[qq]);
    }
    #pragma unroll
    for (int qq = 0; qq < 8; qq++)
        out[(size_t)(b * Qn + q0 + qq) * Vn + tid] = acc[qq] * invs[qq];
}

extern "C" void kernel_launch(void* const* d_in, const int* in_sizes, int n_in,
                              void* d_out, int out_size) {
    const float* queries    = (const float*)d_in[0];  // [4,256,256]
    const float* keys       = (const float*)d_in[1];  // [4,1024,256]
    const float* values     = (const float*)d_in[2];  // [4,1024,256]
    const int*   valid_lens = (const int*)  d_in[3];  // [4]
    const float* W_q        = (const float*)d_in[4];  // [128,256]
    const float* W_k        = (const float*)d_in[5];  // [128,256]
    const float* w_v        = (const float*)d_in[6];  // [128]
    float* out              = (float*)d_out;          // [4,256,256]

    proj_gemm<<<160, 256>>>(queries, keys, W_q, W_k);
    score_kernel<<<B_ * 64, 256>>>(valid_lens, w_v);
    softmax_av<<<B_ * 32, 256>>>(values, valid_lens, out);
}

// round 4
// speedup vs baseline: 1.6624x; 1.6266x over previous
#include <cuda_runtime.h>

#define B_    4
#define Qn    256
#define Kn    1024
#define Din   256
#define H_    128
#define Vn    256

// Scratch (no cudaMalloc allowed)
__device__ float d_qproj[B_ * Qn * H_];          // [b*Q+q][h]
__device__ float d_kproj[B_ * Kn * H_];          // [b*K+k][h]
__device__ float d_scores[B_ * Qn * Kn];         // [b][q][k]  (attn after normalize)
__device__ float d_WqT[Din * H_];                // [i][h]
__device__ float d_WkT[Din * H_];                // [i][h]

__device__ __forceinline__ float tanh_fast(float x) {
    float y;
    asm("tanh.approx.f32 %0, %1;" : "=f"(y) : "f"(x));
    return y;
}

// ---------------------------------------------------------------------------
// Kernel 0: transpose W [H,Din] -> WT [Din,H].  64 blocks, 256 threads.
// ---------------------------------------------------------------------------
__global__ __launch_bounds__(256) void transpose_w(const float* __restrict__ Wq,
                                                   const float* __restrict__ Wk) {
    const int blk = blockIdx.x;
    const int mat = blk >> 5;                 // 0: Wq, 1: Wk
    const int t   = blk & 31;                 // 32 tiles: 8 i-tiles x 4 h-tiles
    const int i0 = (t >> 2) * 32;             // over Din
    const int h0 = (t & 3) * 32;              // over H
    const float* __restrict__ W = mat ? Wk : Wq;
    float* __restrict__ WT      = mat ? d_WkT : d_WqT;

    __shared__ float ts[32][33];
    const int tx = threadIdx.x & 31, ty = threadIdx.x >> 5;
    #pragma unroll
    for (int r = 0; r < 4; r++)
        ts[ty + 8 * r][tx] = W[(h0 + ty + 8 * r) * Din + i0 + tx];
    __syncthreads();
    #pragma unroll
    for (int r = 0; r < 4; r++)
        WT[(i0 + ty + 8 * r) * H_ + h0 + tx] = ts[tx][ty + 8 * r];
}

// ---------------------------------------------------------------------------
// Kernel 1: projection GEMM.  out[row][h] = dot(X[row,:], WT[:,h])
// BM=16, BN=128(H), BK=32.  256 threads, 2x4 microtile.
// Blocks 0..63: queries.  64..319: keys.  grid=320.
// ---------------------------------------------------------------------------
__global__ __launch_bounds__(256) void proj_gemm(const float* __restrict__ Xq,
                                                 const float* __restrict__ Xk) {
    const int blk = blockIdx.x;
    const float* X; const float* WT; float* out; int row0;
    if (blk < 64) { X = Xq; WT = d_WqT; out = d_qproj; row0 = blk * 16; }
    else          { X = Xk; WT = d_WkT; out = d_kproj; row0 = (blk - 64) * 16; }

    __shared__ float As[32][17];     // [kk][m]
    __shared__ float Bs[32][128];    // [kk][h]

    const int tid = threadIdx.x;
    const int tx = tid & 31, ty = tid >> 5;
    float acc[2][4] = {};

    for (int k0 = 0; k0 < Din; k0 += 32) {
        if (tid < 128) {
            const int r = tid >> 3, f = tid & 7;
            float4 v = *(const float4*)&X[(row0 + r) * Din + k0 + f * 4];
            As[f * 4 + 0][r] = v.x; As[f * 4 + 1][r] = v.y;
            As[f * 4 + 2][r] = v.z; As[f * 4 + 3][r] = v.w;
        }
        #pragma unroll
        for (int i = 0; i < 4; i++) {
            const int idx = tid + 256 * i;           // 0..1023
            const int kk = idx >> 5, f = idx & 31;
            float4 v = *(const float4*)&WT[(k0 + kk) * H_ + f * 4];
            *(float4*)&Bs[kk][f * 4] = v;
        }
        __syncthreads();

        #pragma unroll
        for (int kk = 0; kk < 32; kk++) {
            const float a0 = As[kk][ty * 2 + 0];
            const float a1 = As[kk][ty * 2 + 1];
            const float4 bv = *(const float4*)&Bs[kk][tx * 4];
            acc[0][0] = fmaf(a0, bv.x, acc[0][0]); acc[0][1] = fmaf(a0, bv.y, acc[0][1]);
            acc[0][2] = fmaf(a0, bv.z, acc[0][2]); acc[0][3] = fmaf(a0, bv.w, acc[0][3]);
            acc[1][0] = fmaf(a1, bv.x, acc[1][0]); acc[1][1] = fmaf(a1, bv.y, acc[1][1]);
            acc[1][2] = fmaf(a1, bv.z, acc[1][2]); acc[1][3] = fmaf(a1, bv.w, acc[1][3]);
        }
        __syncthreads();
    }
    #pragma unroll
    for (int m = 0; m < 2; m++) {
        float4 v = make_float4(acc[m][0], acc[m][1], acc[m][2], acc[m][3]);
        *(float4*)&out[(row0 + ty * 2 + m) * H_ + tx * 4] = v;
    }
}

// ---------------------------------------------------------------------------
// Kernel 2: additive scores, thread-per-pair, no shuffles.
// Block tile: 32q x 64k.  grid = 4b x 8qt x 16kt = 512.
// Warp w: q rows w*4..w*4+3; lane = one k; float4 over h.
// kt smem padded to 132 so lane-over-k LDS.128 is conflict-free.
// ---------------------------------------------------------------------------
__global__ __launch_bounds__(256) void score_kernel(const int* __restrict__ valid_lens,
                                                    const float* __restrict__ wv) {
    const int blk = blockIdx.x;
    const int b   = blk >> 7;
    const int qt  = (blk >> 4) & 7;
    const int ktl = blk & 15;
    const int q0 = qt * 32, k0 = ktl * 64;
    const int valid = valid_lens[b];
    if (k0 >= valid) return;

    __shared__ float kt_s[64][132];
    __shared__ float qs[32 * 128];
    __shared__ float wvs[128];

    const int tid = threadIdx.x, lane = tid & 31, w = tid >> 5;

    // stage q tile (coalesced float4)
    {
        const float4* __restrict__ src = (const float4*)(d_qproj + (b * Qn + q0) * H_);
        #pragma unroll
        for (int i = 0; i < 4; i++)
            ((float4*)qs)[tid + 256 * i] = src[tid + 256 * i];
    }
    if (tid < 128) wvs[tid] = wv[tid];
    // stage k tile (row-major, padded rows)
    #pragma unroll
    for (int i = 0; i < 8; i++) {
        const int idx = tid + 256 * i;           // 0..2047
        const int kl = idx >> 5, f = idx & 31;
        float4 v = *(const float4*)&d_kproj[(b * Kn + k0 + kl) * H_ + f * 4];
        *(float4*)&kt_s[kl][f * 4] = v;
    }
    __syncthreads();

    #pragma unroll 1
    for (int it = 0; it < 8; it++) {
        const int q  = q0 + w * 4 + (it >> 1);
        const int kl = (it & 1) * 32 + lane;
        const float* __restrict__ qrow = qs + (q - q0) * 128;
        float acc0 = 0.f, acc1 = 0.f;
        #pragma unroll 8
        for (int h4 = 0; h4 < 32; h4++) {
            const float4 kv  = *(const float4*)&kt_s[kl][h4 * 4];
            const float4 qv  = *(const float4*)&qrow[h4 * 4];
            const float4 wv4 = *(const float4*)&wvs[h4 * 4];
            acc0 = fmaf(wv4.x, tanh_fast(qv.x + kv.x), acc0);
            acc1 = fmaf(wv4.y, tanh_fast(qv.y + kv.y), acc1);
            acc0 = fmaf(wv4.z, tanh_fast(qv.z + kv.z), acc0);
            acc1 = fmaf(wv4.w, tanh_fast(qv.w + kv.w), acc1);
        }
        d_scores[(b * Qn + q) * Kn + k0 + kl] = acc0 + acc1;
    }
}

// ---------------------------------------------------------------------------
// Kernel 3: per-row masked softmax, in place.  Zero-pads [valid, kpad32).
// grid = 1024 (one block per (b,q) row), 256 threads.
// ---------------------------------------------------------------------------
__global__ __launch_bounds__(256) void softmax_rows(const int* __restrict__ valid_lens) {
    const int b = blockIdx.x >> 8;
    const int q = blockIdx.x & 255;
    const int valid = valid_lens[b];
    const int kpad = (valid + 31) & ~31;
    float* __restrict__ row = d_scores + (b * Qn + q) * Kn;

    __shared__ float red[8];
    const int tid = threadIdx.x, lane = tid & 31, w = tid >> 5;

    float m = -1e30f;
    for (int k = tid; k < valid; k += 256) m = fmaxf(m, row[k]);
    #pragma unroll
    for (int off = 16; off; off >>= 1)
        m = fmaxf(m, __shfl_xor_sync(0xffffffffu, m, off));
    if (lane == 0) red[w] = m;
    __syncthreads();
    m = red[0];
    #pragma unroll
    for (int i = 1; i < 8; i++) m = fmaxf(m, red[i]);
    __syncthreads();

    float s = 0.f;
    for (int k = tid; k < valid; k += 256) {
        const float e = __expf(row[k] - m);
        row[k] = e;                 // safe: each k touched by one thread
        s += e;
    }
    #pragma unroll
    for (int off = 16; off; off >>= 1)
        s += __shfl_xor_sync(0xffffffffu, s, off);
    if (lane == 0) red[w] = s;
    __syncthreads();
    s = red[0];
    #pragma unroll
    for (int i = 1; i < 8; i++) s += red[i];
    const float inv = 1.0f / s;

    for (int k = tid; k < valid; k += 256) row[k] *= inv;
    for (int k = valid + tid; k < kpad; k += 256) row[k] = 0.f;
}

// ---------------------------------------------------------------------------
// Kernel 4: AV GEMM.  C[256q x 256v] = attn[256 x kpad] @ values[kpad x 256].
// Tile 32q x 64v, BK=32.  grid = 4b x 8qt x 4vt = 128.  2x4 microtile.
// ---------------------------------------------------------------------------
__global__ __launch_bounds__(256) void av_gemm(const float* __restrict__ values,
                                               const int* __restrict__ valid_lens,
                                               float* __restrict__ out) {
    const int blk = blockIdx.x;
    const int b  = blk >> 5;
    const int qt = (blk >> 2) & 7;
    const int vt = blk & 3;
    const int q0 = qt * 32, v0 = vt * 64;
    const int kmax = (valid_lens[b] + 31) & ~31;

    __shared__ float As[32][33];     // [kk][q]
    __shared__ float Bs[32][64];     // [kk][v]

    const int tid = threadIdx.x;
    const int tx = tid & 15, ty = tid >> 4;
    float acc[2][4] = {};

    for (int k0 = 0; k0 < kmax; k0 += 32) {
        {
            const int r = tid >> 3, f = tid & 7;
            float4 v = *(const float4*)&d_scores[(b * Qn + q0 + r) * Kn + k0 + f * 4];
            As[f * 4 + 0][r] = v.x; As[f * 4 + 1][r] = v.y;
            As[f * 4 + 2][r] = v.z; As[f * 4 + 3][r] = v.w;
        }
        #pragma unroll
        for (int i = 0; i < 2; i++) {
            const int idx = tid + 256 * i;       // 0..511
            const int kk = idx >> 4, f = idx & 15;
            float4 v = *(const float4*)&values[((size_t)b * Kn + k0 + kk) * Vn + v0 + f * 4];
            *(float4*)&Bs[kk][f * 4] = v;
        }
        __syncthreads();

        #pragma unroll
        for (int kk = 0; kk < 32; kk++) {
            const float a0 = As[kk][ty * 2 + 0];
            const float a1 = As[kk][ty * 2 + 1];
            const float4 bv = *(const float4*)&Bs[kk][tx * 4];
            acc[0][0] = fmaf(a0, bv.x, acc[0][0]); acc[0][1] = fmaf(a0, bv.y, acc[0][1]);
            acc[0][2] = fmaf(a0, bv.z, acc[0][2]); acc[0][3] = fmaf(a0, bv.w, acc[0][3]);
            acc[1][0] = fmaf(a1, bv.x, acc[1][0]); acc[1][1] = fmaf(a1, bv.y, acc[1][1]);
            acc[1][2] = fmaf(a1, bv.z, acc[1][2]); acc[1][3] = fmaf(a1, bv.w, acc[1][3]);
        }
        __syncthreads();
    }
    #pragma unroll
    for (int m = 0; m < 2; m++) {
        float4 v = make_float4(acc[m][0], acc[m][1], acc[m][2], acc[m][3]);
        *(float4*)&out[((size_t)b * Qn + q0 + ty * 2 + m) * Vn + v0 + tx * 4] = v;
    }
}

extern "C" void kernel_launch(void* const* d_in, const int* in_sizes, int n_in,
                              void* d_out, int out_size) {
    const float* queries    = (const float*)d_in[0];  // [4,256,256]
    const float* keys       = (const float*)d_in[1];  // [4,1024,256]
    const float* values     = (const float*)d_in[2];  // [4,1024,256]
    const int*   valid_lens = (const int*)  d_in[3];  // [4]
    const float* W_q        = (const float*)d_in[4];  // [128,256]
    const float* W_k        = (const float*)d_in[5];  // [128,256]
    const float* w_v        = (const float*)d_in[6];  // [128]
    float* out              = (float*)d_out;          // [4,256,256]

    transpose_w<<<64, 256>>>(W_q, W_k);
    proj_gemm<<<320, 256>>>(queries, keys);
    score_kernel<<<512, 256>>>(valid_lens, w_v);
    softmax_rows<<<1024, 256>>>(valid_lens);
    av_gemm<<<128, 256>>>(values, valid_lens, out);
}

// round 5
// speedup vs baseline: 1.6695x; 1.0043x over previous
#include <cuda_runtime.h>

#define B_    4
#define Qn    256
#define Kn    1024
#define Din   256
#define H_    128
#define Vn    256

// Scratch (no cudaMalloc allowed)
__device__ float d_qproj[B_ * Qn * H_];          // [b*Q+q][h]
__device__ float d_kproj[B_ * Kn * H_];          // [b*K+k][h]
__device__ float d_scores[B_ * Qn * Kn];         // p = exp(score - B), zero beyond valid
__device__ float d_WqT[Din * H_];                // [i][h]
__device__ float d_WkT[Din * H_];                // [i][h]
__device__ float d_B;                            // exp shift = sum |w_v|

__device__ __forceinline__ float tanh_fast(float x) {
    float y;
    asm("tanh.approx.f32 %0, %1;" : "=f"(y) : "f"(x));
    return y;
}

// ---------------------------------------------------------------------------
// Kernel 0: transpose W [H,Din] -> WT [Din,H]  (blocks 0..63)
//           block 64: d_B = sum |w_v|
// ---------------------------------------------------------------------------
__global__ __launch_bounds__(256) void transpose_w(const float* __restrict__ Wq,
                                                   const float* __restrict__ Wk,
                                                   const float* __restrict__ wv) {
    const int blk = blockIdx.x;
    if (blk == 64) {
        if (threadIdx.x < 32) {
            float s = 0.f;
            #pragma unroll
            for (int i = 0; i < 4; i++) s += fabsf(wv[threadIdx.x + 32 * i]);
            #pragma unroll
            for (int off = 16; off; off >>= 1)
                s += __shfl_xor_sync(0xffffffffu, s, off);
            if (threadIdx.x == 0) d_B = s;
        }
        return;
    }
    const int mat = blk >> 5;
    const int t   = blk & 31;
    const int i0 = (t >> 2) * 32;
    const int h0 = (t & 3) * 32;
    const float* __restrict__ W = mat ? Wk : Wq;
    float* __restrict__ WT      = mat ? d_WkT : d_WqT;

    __shared__ float ts[32][33];
    const int tx = threadIdx.x & 31, ty = threadIdx.x >> 5;
    #pragma unroll
    for (int r = 0; r < 4; r++)
        ts[ty + 8 * r][tx] = W[(h0 + ty + 8 * r) * Din + i0 + tx];
    __syncthreads();
    #pragma unroll
    for (int r = 0; r < 4; r++)
        WT[(i0 + ty + 8 * r) * H_ + h0 + tx] = ts[tx][ty + 8 * r];
}

// ---------------------------------------------------------------------------
// Kernel 1: projection GEMM.  out[row][h] = dot(X[row,:], WT[:,h])
// BM=16, BN=128(H), BK=32.  256 threads, 2x4 microtile.  grid=320.
// ---------------------------------------------------------------------------
__global__ __launch_bounds__(256) void proj_gemm(const float* __restrict__ Xq,
                                                 const float* __restrict__ Xk) {
    const int blk = blockIdx.x;
    const float* X; const float* WT; float* out; int row0;
    if (blk < 64) { X = Xq; WT = d_WqT; out = d_qproj; row0 = blk * 16; }
    else          { X = Xk; WT = d_WkT; out = d_kproj; row0 = (blk - 64) * 16; }

    __shared__ float As[32][17];
    __shared__ float Bs[32][128];

    const int tid = threadIdx.x;
    const int tx = tid & 31, ty = tid >> 5;
    float acc[2][4] = {};

    for (int k0 = 0; k0 < Din; k0 += 32) {
        if (tid < 128) {
            const int r = tid >> 3, f = tid & 7;
            float4 v = *(const float4*)&X[(row0 + r) * Din + k0 + f * 4];
            As[f * 4 + 0][r] = v.x; As[f * 4 + 1][r] = v.y;
            As[f * 4 + 2][r] = v.z; As[f * 4 + 3][r] = v.w;
        }
        #pragma unroll
        for (int i = 0; i < 4; i++) {
            const int idx = tid + 256 * i;
            const int kk = idx >> 5, f = idx & 31;
            *(float4*)&Bs[kk][f * 4] = *(const float4*)&WT[(k0 + kk) * H_ + f * 4];
        }
        __syncthreads();

        #pragma unroll
        for (int kk = 0; kk < 32; kk++) {
            const float a0 = As[kk][ty * 2 + 0];
            const float a1 = As[kk][ty * 2 + 1];
            const float4 bv = *(const float4*)&Bs[kk][tx * 4];
            acc[0][0] = fmaf(a0, bv.x, acc[0][0]); acc[0][1] = fmaf(a0, bv.y, acc[0][1]);
            acc[0][2] = fmaf(a0, bv.z, acc[0][2]); acc[0][3] = fmaf(a0, bv.w, acc[0][3]);
            acc[1][0] = fmaf(a1, bv.x, acc[1][0]); acc[1][1] = fmaf(a1, bv.y, acc[1][1]);
            acc[1][2] = fmaf(a1, bv.z, acc[1][2]); acc[1][3] = fmaf(a1, bv.w, acc[1][3]);
        }
        __syncthreads();
    }
    #pragma unroll
    for (int m = 0; m < 2; m++) {
        float4 v = make_float4(acc[m][0], acc[m][1], acc[m][2], acc[m][3]);
        *(float4*)&out[(row0 + ty * 2 + m) * H_ + tx * 4] = v;
    }
}

// ---------------------------------------------------------------------------
// Kernel 2: scores -> p = exp(score - B), zero beyond valid.
// Block tile 32q x 64k.  grid = 4b x 8qt x 16kt = 512.
// Warp w: k = (w&1)*32 + lane, q rows (w>>1)*8 .. +8.
// kv chunks held in registers, reused across 8 q rows.
// ---------------------------------------------------------------------------
__global__ __launch_bounds__(256) void score_kernel(const int* __restrict__ valid_lens,
                                                    const float* __restrict__ wv) {
    const int blk = blockIdx.x;
    const int b   = blk >> 7;
    const int qt  = (blk >> 4) & 7;
    const int ktl = blk & 15;
    const int q0 = qt * 32, k0 = ktl * 64;
    const int valid = valid_lens[b];
    if (k0 >= valid) return;

    __shared__ float kt_s[64][132];
    __shared__ float qs[32 * 128];
    __shared__ float wvs[128];

    const int tid = threadIdx.x, lane = tid & 31, w = tid >> 5;

    {
        const float4* __restrict__ src = (const float4*)(d_qproj + (b * Qn + q0) * H_);
        #pragma unroll
        for (int i = 0; i < 4; i++)
            ((float4*)qs)[tid + 256 * i] = src[tid + 256 * i];
    }
    if (tid < 128) wvs[tid] = wv[tid];
    #pragma unroll
    for (int i = 0; i < 8; i++) {
        const int idx = tid + 256 * i;
        const int kl = idx >> 5, f = idx & 31;
        *(float4*)&kt_s[kl][f * 4] =
            *(const float4*)&d_kproj[(b * Kn + k0 + kl) * H_ + f * 4];
    }
    const float Bsh = d_B;
    __syncthreads();

    const int klh = (w & 1) * 32 + lane;     // local k: 0..63
    const int qb  = (w >> 1) * 8;            // q group base
    const int kg  = k0 + klh;                // global k

    float acc[8] = {};
    #pragma unroll
    for (int h0 = 0; h0 < 128; h0 += 16) {
        const float4 kv0 = *(const float4*)&kt_s[klh][h0 + 0];
        const float4 kv1 = *(const float4*)&kt_s[klh][h0 + 4];
        const float4 kv2 = *(const float4*)&kt_s[klh][h0 + 8];
        const float4 kv3 = *(const float4*)&kt_s[klh][h0 + 12];
        const float4 w0 = *(const float4*)&wvs[h0 + 0];
        const float4 w1 = *(const float4*)&wvs[h0 + 4];
        const float4 w2 = *(const float4*)&wvs[h0 + 8];
        const float4 w3 = *(const float4*)&wvs[h0 + 12];
        #pragma unroll
        for (int qi = 0; qi < 8; qi++) {
            const float* __restrict__ qrow = qs + (qb + qi) * 128 + h0;
            const float4 q0v = *(const float4*)&qrow[0];
            const float4 q1v = *(const float4*)&qrow[4];
            const float4 q2v = *(const float4*)&qrow[8];
            const float4 q3v = *(const float4*)&qrow[12];
            float a = acc[qi];
            a = fmaf(w0.x, tanh_fast(q0v.x + kv0.x), a);
            a = fmaf(w0.y, tanh_fast(q0v.y + kv0.y), a);
            a = fmaf(w0.z, tanh_fast(q0v.z + kv0.z), a);
            a = fmaf(w0.w, tanh_fast(q0v.w + kv0.w), a);
            a = fmaf(w1.x, tanh_fast(q1v.x + kv1.x), a);
            a = fmaf(w1.y, tanh_fast(q1v.y + kv1.y), a);
            a = fmaf(w1.z, tanh_fast(q1v.z + kv1.z), a);
            a = fmaf(w1.w, tanh_fast(q1v.w + kv1.w), a);
            a = fmaf(w2.x, tanh_fast(q2v.x + kv2.x), a);
            a = fmaf(w2.y, tanh_fast(q2v.y + kv2.y), a);
            a = fmaf(w2.z, tanh_fast(q2v.z + kv2.z), a);
            a = fmaf(w2.w, tanh_fast(q2v.w + kv2.w), a);
            a = fmaf(w3.x, tanh_fast(q3v.x + kv3.x), a);
            a = fmaf(w3.y, tanh_fast(q3v.y + kv3.y), a);
            a = fmaf(w3.z, tanh_fast(q3v.z + kv3.z), a);
            a = fmaf(w3.w, tanh_fast(q3v.w + kv3.w), a);
            acc[qi] = a;
        }
    }

    const bool live = (kg < valid);
    #pragma unroll
    for (int qi = 0; qi < 8; qi++) {
        const float p = live ? __expf(acc[qi] - Bsh) : 0.f;
        d_scores[(b * Qn + q0 + qb + qi) * Kn + kg] = p;
    }
}

// ---------------------------------------------------------------------------
// Kernel 3: AV GEMM with inline normalization.
// out[q][v] = (sum_k p[q][k] * V[k][v]) / (sum_k p[q][k])
// Tile 32q x 64v, BK=32.  grid = 128.  2x4 microtile.
// Row sums come free: every thread already reads a0/a1 each kk.
// ---------------------------------------------------------------------------
__global__ __launch_bounds__(256) void av_gemm(const float* __restrict__ values,
                                               const int* __restrict__ valid_lens,
                                               float* __restrict__ out) {
    const int blk = blockIdx.x;
    const int b  = blk >> 5;
    const int qt = (blk >> 2) & 7;
    const int vt = blk & 3;
    const int q0 = qt * 32, v0 = vt * 64;
    const int kmax = (valid_lens[b] + 31) & ~31;

    __shared__ float As[32][33];
    __shared__ float Bs[32][64];

    const int tid = threadIdx.x;
    const int tx = tid & 15, ty = tid >> 4;
    float acc[2][4] = {};
    float sum0 = 0.f, sum1 = 0.f;

    for (int k0 = 0; k0 < kmax; k0 += 32) {
        {
            const int r = tid >> 3, f = tid & 7;
            float4 v = *(const float4*)&d_scores[(b * Qn + q0 + r) * Kn + k0 + f * 4];
            As[f * 4 + 0][r] = v.x; As[f * 4 + 1][r] = v.y;
            As[f * 4 + 2][r] = v.z; As[f * 4 + 3][r] = v.w;
        }
        #pragma unroll
        for (int i = 0; i < 2; i++) {
            const int idx = tid + 256 * i;
            const int kk = idx >> 4, f = idx & 15;
            *(float4*)&Bs[kk][f * 4] =
                *(const float4*)&values[((size_t)b * Kn + k0 + kk) * Vn + v0 + f * 4];
        }
        __syncthreads();

        #pragma unroll
        for (int kk = 0; kk < 32; kk++) {
            const float a0 = As[kk][ty * 2 + 0];
            const float a1 = As[kk][ty * 2 + 1];
            sum0 += a0; sum1 += a1;
            const float4 bv = *(const float4*)&Bs[kk][tx * 4];
            acc[0][0] = fmaf(a0, bv.x, acc[0][0]); acc[0][1] = fmaf(a0, bv.y, acc[0][1]);
            acc[0][2] = fmaf(a0, bv.z, acc[0][2]); acc[0][3] = fmaf(a0, bv.w, acc[0][3]);
            acc[1][0] = fmaf(a1, bv.x, acc[1][0]); acc[1][1] = fmaf(a1, bv.y, acc[1][1]);
            acc[1][2] = fmaf(a1, bv.z, acc[1][2]); acc[1][3] = fmaf(a1, bv.w, acc[1][3]);
        }
        __syncthreads();
    }
    const float inv0 = 1.0f / sum0;
    const float inv1 = 1.0f / sum1;
    {
        float4 v = make_float4(acc[0][0] * inv0, acc[0][1] * inv0,
                               acc[0][2] * inv0, acc[0][3] * inv0);
        *(float4*)&out[((size_t)b * Qn + q0 + ty * 2 + 0) * Vn + v0 + tx * 4] = v;
        float4 v2 = make_float4(acc[1][0] * inv1, acc[1][1] * inv1,
                                acc[1][2] * inv1, acc[1][3] * inv1);
        *(float4*)&out[((size_t)b * Qn + q0 + ty * 2 + 1) * Vn + v0 + tx * 4] = v2;
    }
}

extern "C" void kernel_launch(void* const* d_in, const int* in_sizes, int n_in,
                              void* d_out, int out_size) {
    const float* queries    = (const float*)d_in[0];
    const float* keys       = (const float*)d_in[1];
    const float* values     = (const float*)d_in[2];
    const int*   valid_lens = (const int*)  d_in[3];
    const float* W_q        = (const float*)d_in[4];
    const float* W_k        = (const float*)d_in[5];
    const float* w_v        = (const float*)d_in[6];
    float* out              = (float*)d_out;

    transpose_w<<<65, 256>>>(W_q, W_k, w_v);
    proj_gemm<<<320, 256>>>(queries, keys);
    score_kernel<<<512, 256>>>(valid_lens, w_v);
    av_gemm<<<128, 256>>>(values, valid_lens, out);
}

// round 6
// speedup vs baseline: 1.8096x; 1.0839x over previous
#include <cuda_runtime.h>

#define B_    4
#define Qn    256
#define Kn    1024
#define Din   256
#define H_    128
#define Vn    256

// Scratch (no cudaMalloc allowed)
__device__ float d_qproj[B_ * Qn * H_];          // [b*Q+q][h]
__device__ float d_kproj[B_ * Kn * H_];          // [b*K+k][h]
__device__ float d_scores[B_ * Qn * Kn];         // p = exp(score - B), zero beyond valid
__device__ float d_WqT[Din * H_];                // [i][h]
__device__ float d_WkT[Din * H_];                // [i][h]
__device__ float d_B;                            // exp shift = sum |w_v|

__device__ __forceinline__ float tanh_fast(float x) {
    float y;
    asm("tanh.approx.f32 %0, %1;" : "=f"(y) : "f"(x));
    return y;
}

// ---------------------------------------------------------------------------
// Kernel 0: transpose W [H,Din] -> WT [Din,H]  (blocks 0..63)
//           block 64: d_B = sum |w_v|
// ---------------------------------------------------------------------------
__global__ __launch_bounds__(256) void transpose_w(const float* __restrict__ Wq,
                                                   const float* __restrict__ Wk,
                                                   const float* __restrict__ wv) {
    const int blk = blockIdx.x;
    if (blk == 64) {
        if (threadIdx.x < 32) {
            float s = 0.f;
            #pragma unroll
            for (int i = 0; i < 4; i++) s += fabsf(wv[threadIdx.x + 32 * i]);
            #pragma unroll
            for (int off = 16; off; off >>= 1)
                s += __shfl_xor_sync(0xffffffffu, s, off);
            if (threadIdx.x == 0) d_B = s;
        }
        return;
    }
    const int mat = blk >> 5;
    const int t   = blk & 31;
    const int i0 = (t >> 2) * 32;
    const int h0 = (t & 3) * 32;
    const float* __restrict__ W = mat ? Wk : Wq;
    float* __restrict__ WT      = mat ? d_WkT : d_WqT;

    __shared__ float ts[32][33];
    const int tx = threadIdx.x & 31, ty = threadIdx.x >> 5;
    #pragma unroll
    for (int r = 0; r < 4; r++)
        ts[ty + 8 * r][tx] = W[(h0 + ty + 8 * r) * Din + i0 + tx];
    __syncthreads();
    #pragma unroll
    for (int r = 0; r < 4; r++)
        WT[(i0 + ty + 8 * r) * H_ + h0 + tx] = ts[tx][ty + 8 * r];
}

// ---------------------------------------------------------------------------
// Kernel 1: projection GEMM.  out[row][h] = dot(X[row,:], WT[:,h])
// BM=16, BN=128(H), BK=32.  256 threads, 2x4 microtile.  grid=320.
// ---------------------------------------------------------------------------
__global__ __launch_bounds__(256) void proj_gemm(const float* __restrict__ Xq,
                                                 const float* __restrict__ Xk) {
    const int blk = blockIdx.x;
    const float* X; const float* WT; float* out; int row0;
    if (blk < 64) { X = Xq; WT = d_WqT; out = d_qproj; row0 = blk * 16; }
    else          { X = Xk; WT = d_WkT; out = d_kproj; row0 = (blk - 64) * 16; }

    __shared__ float As[32][17];
    __shared__ float Bs[32][128];

    const int tid = threadIdx.x;
    const int tx = tid & 31, ty = tid >> 5;
    float acc[2][4] = {};

    for (int k0 = 0; k0 < Din; k0 += 32) {
        if (tid < 128) {
            const int r = tid >> 3, f = tid & 7;
            float4 v = *(const float4*)&X[(row0 + r) * Din + k0 + f * 4];
            As[f * 4 + 0][r] = v.x; As[f * 4 + 1][r] = v.y;
            As[f * 4 + 2][r] = v.z; As[f * 4 + 3][r] = v.w;
        }
        #pragma unroll
        for (int i = 0; i < 4; i++) {
            const int idx = tid + 256 * i;
            const int kk = idx >> 5, f = idx & 31;
            *(float4*)&Bs[kk][f * 4] = *(const float4*)&WT[(k0 + kk) * H_ + f * 4];
        }
        __syncthreads();

        #pragma unroll
        for (int kk = 0; kk < 32; kk++) {
            const float a0 = As[kk][ty * 2 + 0];
            const float a1 = As[kk][ty * 2 + 1];
            const float4 bv = *(const float4*)&Bs[kk][tx * 4];
            acc[0][0] = fmaf(a0, bv.x, acc[0][0]); acc[0][1] = fmaf(a0, bv.y, acc[0][1]);
            acc[0][2] = fmaf(a0, bv.z, acc[0][2]); acc[0][3] = fmaf(a0, bv.w, acc[0][3]);
            acc[1][0] = fmaf(a1, bv.x, acc[1][0]); acc[1][1] = fmaf(a1, bv.y, acc[1][1]);
            acc[1][2] = fmaf(a1, bv.z, acc[1][2]); acc[1][3] = fmaf(a1, bv.w, acc[1][3]);
        }
        __syncthreads();
    }
    #pragma unroll
    for (int m = 0; m < 2; m++) {
        float4 v = make_float4(acc[m][0], acc[m][1], acc[m][2], acc[m][3]);
        *(float4*)&out[(row0 + ty * 2 + m) * H_ + tx * 4] = v;
    }
}

// ---------------------------------------------------------------------------
// Kernel 2: scores -> p = exp(score - B), zero beyond valid.
// Block tile 32q x 64k.  grid = 512.  (unchanged from R4)
// ---------------------------------------------------------------------------
__global__ __launch_bounds__(256) void score_kernel(const int* __restrict__ valid_lens,
                                                    const float* __restrict__ wv) {
    const int blk = blockIdx.x;
    const int b   = blk >> 7;
    const int qt  = (blk >> 4) & 7;
    const int ktl = blk & 15;
    const int q0 = qt * 32, k0 = ktl * 64;
    const int valid = valid_lens[b];
    if (k0 >= valid) return;

    __shared__ float kt_s[64][132];
    __shared__ float qs[32 * 128];
    __shared__ float wvs[128];

    const int tid = threadIdx.x, lane = tid & 31, w = tid >> 5;

    {
        const float4* __restrict__ src = (const float4*)(d_qproj + (b * Qn + q0) * H_);
        #pragma unroll
        for (int i = 0; i < 4; i++)
            ((float4*)qs)[tid + 256 * i] = src[tid + 256 * i];
    }
    if (tid < 128) wvs[tid] = wv[tid];
    #pragma unroll
    for (int i = 0; i < 8; i++) {
        const int idx = tid + 256 * i;
        const int kl = idx >> 5, f = idx & 31;
        *(float4*)&kt_s[kl][f * 4] =
            *(const float4*)&d_kproj[(b * Kn + k0 + kl) * H_ + f * 4];
    }
    const float Bsh = d_B;
    __syncthreads();

    const int klh = (w & 1) * 32 + lane;
    const int qb  = (w >> 1) * 8;
    const int kg  = k0 + klh;

    float acc[8] = {};
    #pragma unroll
    for (int h0 = 0; h0 < 128; h0 += 16) {
        const float4 kv0 = *(const float4*)&kt_s[klh][h0 + 0];
        const float4 kv1 = *(const float4*)&kt_s[klh][h0 + 4];
        const float4 kv2 = *(const float4*)&kt_s[klh][h0 + 8];
        const float4 kv3 = *(const float4*)&kt_s[klh][h0 + 12];
        const float4 w0 = *(const float4*)&wvs[h0 + 0];
        const float4 w1 = *(const float4*)&wvs[h0 + 4];
        const float4 w2 = *(const float4*)&wvs[h0 + 8];
        const float4 w3 = *(const float4*)&wvs[h0 + 12];
        #pragma unroll
        for (int qi = 0; qi < 8; qi++) {
            const float* __restrict__ qrow = qs + (qb + qi) * 128 + h0;
            const float4 q0v = *(const float4*)&qrow[0];
            const float4 q1v = *(const float4*)&qrow[4];
            const float4 q2v = *(const float4*)&qrow[8];
            const float4 q3v = *(const float4*)&qrow[12];
            float a = acc[qi];
            a = fmaf(w0.x, tanh_fast(q0v.x + kv0.x), a);
            a = fmaf(w0.y, tanh_fast(q0v.y + kv0.y), a);
            a = fmaf(w0.z, tanh_fast(q0v.z + kv0.z), a);
            a = fmaf(w0.w, tanh_fast(q0v.w + kv0.w), a);
            a = fmaf(w1.x, tanh_fast(q1v.x + kv1.x), a);
            a = fmaf(w1.y, tanh_fast(q1v.y + kv1.y), a);
            a = fmaf(w1.z, tanh_fast(q1v.z + kv1.z), a);
            a = fmaf(w1.w, tanh_fast(q1v.w + kv1.w), a);
            a = fmaf(w2.x, tanh_fast(q2v.x + kv2.x), a);
            a = fmaf(w2.y, tanh_fast(q2v.y + kv2.y), a);
            a = fmaf(w2.z, tanh_fast(q2v.z + kv2.z), a);
            a = fmaf(w2.w, tanh_fast(q2v.w + kv2.w), a);
            a = fmaf(w3.x, tanh_fast(q3v.x + kv3.x), a);
            a = fmaf(w3.y, tanh_fast(q3v.y + kv3.y), a);
            a = fmaf(w3.z, tanh_fast(q3v.z + kv3.z), a);
            a = fmaf(w3.w, tanh_fast(q3v.w + kv3.w), a);
            acc[qi] = a;
        }
    }

    const bool live = (kg < valid);
    #pragma unroll
    for (int qi = 0; qi < 8; qi++) {
        const float p = live ? __expf(acc[qi] - Bsh) : 0.f;
        d_scores[(b * Qn + q0 + qb + qi) * Kn + kg] = p;
    }
}

// ---------------------------------------------------------------------------
// Kernel 3: AV GEMM + inline normalize.  RESTRUCTURED:
// Tile 16q x 64v, BK=64.  grid = 4b x 16qt x 4vt = 256.  256 threads.
// Thread (ty=q row, tx=v/4): 1x4 outputs + row sum.
// A tile kept [q][k] (gmem layout) -> LDS.128 per 4 kk.
// Global loads software-pipelined through registers.
// ---------------------------------------------------------------------------
__global__ __launch_bounds__(256) void av_gemm(const float* __restrict__ values,
                                               const int* __restrict__ valid_lens,
                                               float* __restrict__ out) {
    const int blk = blockIdx.x;
    const int b  = blk >> 6;
    const int qt = (blk >> 2) & 15;
    const int vt = blk & 3;
    const int q0 = qt * 16, v0 = vt * 64;
    const int kmax = (valid_lens[b] + 63) & ~63;   // scores zeroed to 64-boundary
    const int nPh = kmax >> 6;

    __shared__ float As[16][68];     // [q][kk]  (16B-aligned rows: 68*4=272)
    __shared__ float Bs[64][68];     // [kk][v]

    const int tid = threadIdx.x;
    const int tx = tid & 15, ty = tid >> 4;

    // load indices
    const int ar = tid >> 4, af = tid & 15;                    // As: row, f4
    const float* __restrict__ arow = d_scores + (b * Qn + q0 + ar) * Kn + af * 4;
    const float* __restrict__ vbase = values + (size_t)b * Kn * Vn + v0;

    float4 pa;
    float4 pb[4];
    // prologue: phase 0 loads
    pa = *(const float4*)&arow[0];
    #pragma unroll
    for (int i = 0; i < 4; i++) {
        const int idx = tid + 256 * i;
        const int kk = idx >> 4, f = idx & 15;
        pb[i] = *(const float4*)&vbase[(size_t)kk * Vn + f * 4];
    }

    float4 acc = make_float4(0.f, 0.f, 0.f, 0.f);
    float sum = 0.f;

    for (int ph = 0; ph < nPh; ph++) {
        // commit prefetched regs to smem
        *(float4*)&As[ar][af * 4] = pa;
        #pragma unroll
        for (int i = 0; i < 4; i++) {
            const int idx = tid + 256 * i;
            const int kk = idx >> 4, f = idx & 15;
            *(float4*)&Bs[kk][f * 4] = pb[i];
        }
        __syncthreads();

        // prefetch next phase (overlaps with compute below)
        if (ph + 1 < nPh) {
            const int k0n = (ph + 1) * 64;
            pa = *(const float4*)&arow[k0n];
            #pragma unroll
            for (int i = 0; i < 4; i++) {
                const int idx = tid + 256 * i;
                const int kk = idx >> 4, f = idx & 15;
                pb[i] = *(const float4*)&vbase[(size_t)(k0n + kk) * Vn + f * 4];
            }
        }

        // compute 64 kk
        #pragma unroll
        for (int kk4 = 0; kk4 < 16; kk4++) {
            const float4 av = *(const float4*)&As[ty][kk4 * 4];
            sum += (av.x + av.y) + (av.z + av.w);
            {
                const float4 bv = *(const float4*)&Bs[kk4 * 4 + 0][tx * 4];
                acc.x = fmaf(av.x, bv.x, acc.x); acc.y = fmaf(av.x, bv.y, acc.y);
                acc.z = fmaf(av.x, bv.z, acc.z); acc.w = fmaf(av.x, bv.w, acc.w);
            }
            {
                const float4 bv = *(const float4*)&Bs[kk4 * 4 + 1][tx * 4];
                acc.x = fmaf(av.y, bv.x, acc.x); acc.y = fmaf(av.y, bv.y, acc.y);
                acc.z = fmaf(av.y, bv.z, acc.z); acc.w = fmaf(av.y, bv.w, acc.w);
            }
            {
                const float4 bv = *(const float4*)&Bs[kk4 * 4 + 2][tx * 4];
                acc.x = fmaf(av.z, bv.x, acc.x); acc.y = fmaf(av.z, bv.y, acc.y);
                acc.z = fmaf(av.z, bv.z, acc.z); acc.w = fmaf(av.z, bv.w, acc.w);
            }
            {
                const float4 bv = *(const float4*)&Bs[kk4 * 4 + 3][tx * 4];
                acc.x = fmaf(av.w, bv.x, acc.x); acc.y = fmaf(av.w, bv.y, acc.y);
                acc.z = fmaf(av.w, bv.z, acc.z); acc.w = fmaf(av.w, bv.w, acc.w);
            }
        }
        __syncthreads();
    }

    const float inv = 1.0f / sum;
    float4 o = make_float4(acc.x * inv, acc.y * inv, acc.z * inv, acc.w * inv);
    *(float4*)&out[((size_t)b * Qn + q0 + ty) * Vn + v0 + tx * 4] = o;
}

extern "C" void kernel_launch(void* const* d_in, const int* in_sizes, int n_in,
                              void* d_out, int out_size) {
    const float* queries    = (const float*)d_in[0];
    const float* keys       = (const float*)d_in[1];
    const float* values     = (const float*)d_in[2];
    const int*   valid_lens = (const int*)  d_in[3];
    const float* W_q        = (const float*)d_in[4];
    const float* W_k        = (const float*)d_in[5];
    const float* w_v        = (const float*)d_in[6];
    float* out              = (float*)d_out;

    transpose_w<<<65, 256>>>(W_q, W_k, w_v);
    proj_gemm<<<320, 256>>>(queries, keys);
    score_kernel<<<512, 256>>>(valid_lens, w_v);
    av_gemm<<<256, 256>>>(values, valid_lens, out);
}

// round 7
// speedup vs baseline: 1.8226x; 1.0072x over previous
#include <cuda_runtime.h>

#define B_    4
#define Qn    256
#define Kn    1024
#define Din   256
#define H_    128
#define Vn    256

// Scratch (no cudaMalloc allowed)
__device__ float d_qproj[B_ * Qn * H_];          // [b*Q+q][h]
__device__ float d_kproj[B_ * Kn * H_];          // [b*K+k][h]
__device__ float d_scores[B_ * Qn * Kn];         // p = exp(score - B), zero beyond valid
__device__ float d_WqT[Din * H_];                // [i][h]
__device__ float d_WkT[Din * H_];                // [i][h]
__device__ float d_B;                            // exp shift = sum |w_v|

__device__ __forceinline__ float tanh_fast(float x) {
    float y;
    asm("tanh.approx.f32 %0, %1;" : "=f"(y) : "f"(x));
    return y;
}

// ---------------------------------------------------------------------------
// Kernel 0: transpose W [H,Din] -> WT [Din,H]  (blocks 0..63)
//           block 64: d_B = sum |w_v|
// ---------------------------------------------------------------------------
__global__ __launch_bounds__(256) void transpose_w(const float* __restrict__ Wq,
                                                   const float* __restrict__ Wk,
                                                   const float* __restrict__ wv) {
    const int blk = blockIdx.x;
    if (blk == 64) {
        if (threadIdx.x < 32) {
            float s = 0.f;
            #pragma unroll
            for (int i = 0; i < 4; i++) s += fabsf(wv[threadIdx.x + 32 * i]);
            #pragma unroll
            for (int off = 16; off; off >>= 1)
                s += __shfl_xor_sync(0xffffffffu, s, off);
            if (threadIdx.x == 0) d_B = s;
        }
        return;
    }
    const int mat = blk >> 5;
    const int t   = blk & 31;
    const int i0 = (t >> 2) * 32;
    const int h0 = (t & 3) * 32;
    const float* __restrict__ W = mat ? Wk : Wq;
    float* __restrict__ WT      = mat ? d_WkT : d_WqT;

    __shared__ float ts[32][33];
    const int tx = threadIdx.x & 31, ty = threadIdx.x >> 5;
    #pragma unroll
    for (int r = 0; r < 4; r++)
        ts[ty + 8 * r][tx] = W[(h0 + ty + 8 * r) * Din + i0 + tx];
    __syncthreads();
    #pragma unroll
    for (int r = 0; r < 4; r++)
        WT[(i0 + ty + 8 * r) * H_ + h0 + tx] = ts[tx][ty + 8 * r];
}

// ---------------------------------------------------------------------------
// Kernel 1: projection GEMM.  out[row][h] = dot(X[row,:], WT[:,h])
// BM=16, BN=128(H), BK=32.  256 threads, 2x4 microtile.  grid=320.
// ---------------------------------------------------------------------------
__global__ __launch_bounds__(256) void proj_gemm(const float* __restrict__ Xq,
                                                 const float* __restrict__ Xk) {
    const int blk = blockIdx.x;
    const float* X; const float* WT; float* out; int row0;
    if (blk < 64) { X = Xq; WT = d_WqT; out = d_qproj; row0 = blk * 16; }
    else          { X = Xk; WT = d_WkT; out = d_kproj; row0 = (blk - 64) * 16; }

    __shared__ float As[32][17];
    __shared__ float Bs[32][128];

    const int tid = threadIdx.x;
    const int tx = tid & 31, ty = tid >> 5;
    float acc[2][4] = {};

    for (int k0 = 0; k0 < Din; k0 += 32) {
        if (tid < 128) {
            const int r = tid >> 3, f = tid & 7;
            float4 v = *(const float4*)&X[(row0 + r) * Din + k0 + f * 4];
            As[f * 4 + 0][r] = v.x; As[f * 4 + 1][r] = v.y;
            As[f * 4 + 2][r] = v.z; As[f * 4 + 3][r] = v.w;
        }
        #pragma unroll
        for (int i = 0; i < 4; i++) {
            const int idx = tid + 256 * i;
            const int kk = idx >> 5, f = idx & 31;
            *(float4*)&Bs[kk][f * 4] = *(const float4*)&WT[(k0 + kk) * H_ + f * 4];
        }
        __syncthreads();

        #pragma unroll
        for (int kk = 0; kk < 32; kk++) {
            const float a0 = As[kk][ty * 2 + 0];
            const float a1 = As[kk][ty * 2 + 1];
            const float4 bv = *(const float4*)&Bs[kk][tx * 4];
            acc[0][0] = fmaf(a0, bv.x, acc[0][0]); acc[0][1] = fmaf(a0, bv.y, acc[0][1]);
            acc[0][2] = fmaf(a0, bv.z, acc[0][2]); acc[0][3] = fmaf(a0, bv.w, acc[0][3]);
            acc[1][0] = fmaf(a1, bv.x, acc[1][0]); acc[1][1] = fmaf(a1, bv.y, acc[1][1]);
            acc[1][2] = fmaf(a1, bv.z, acc[1][2]); acc[1][3] = fmaf(a1, bv.w, acc[1][3]);
        }
        __syncthreads();
    }
    #pragma unroll
    for (int m = 0; m < 2; m++) {
        float4 v = make_float4(acc[m][0], acc[m][1], acc[m][2], acc[m][3]);
        *(float4*)&out[(row0 + ty * 2 + m) * H_ + tx * 4] = v;
    }
}

// ---------------------------------------------------------------------------
// Kernel 2: scores -> p = exp(score - B), zero beyond valid.
// Block tile 32q x 64k.  grid = 512.  (unchanged)
// ---------------------------------------------------------------------------
__global__ __launch_bounds__(256) void score_kernel(const int* __restrict__ valid_lens,
                                                    const float* __restrict__ wv) {
    const int blk = blockIdx.x;
    const int b   = blk >> 7;
    const int qt  = (blk >> 4) & 7;
    const int ktl = blk & 15;
    const int q0 = qt * 32, k0 = ktl * 64;
    const int valid = valid_lens[b];
    if (k0 >= valid) return;

    __shared__ float kt_s[64][132];
    __shared__ float qs[32 * 128];
    __shared__ float wvs[128];

    const int tid = threadIdx.x, lane = tid & 31, w = tid >> 5;

    {
        const float4* __restrict__ src = (const float4*)(d_qproj + (b * Qn + q0) * H_);
        #pragma unroll
        for (int i = 0; i < 4; i++)
            ((float4*)qs)[tid + 256 * i] = src[tid + 256 * i];
    }
    if (tid < 128) wvs[tid] = wv[tid];
    #pragma unroll
    for (int i = 0; i < 8; i++) {
        const int idx = tid + 256 * i;
        const int kl = idx >> 5, f = idx & 31;
        *(float4*)&kt_s[kl][f * 4] =
            *(const float4*)&d_kproj[(b * Kn + k0 + kl) * H_ + f * 4];
    }
    const float Bsh = d_B;
    __syncthreads();

    const int klh = (w & 1) * 32 + lane;
    const int qb  = (w >> 1) * 8;
    const int kg  = k0 + klh;

    float acc[8] = {};
    #pragma unroll
    for (int h0 = 0; h0 < 128; h0 += 16) {
        const float4 kv0 = *(const float4*)&kt_s[klh][h0 + 0];
        const float4 kv1 = *(const float4*)&kt_s[klh][h0 + 4];
        const float4 kv2 = *(const float4*)&kt_s[klh][h0 + 8];
        const float4 kv3 = *(const float4*)&kt_s[klh][h0 + 12];
        const float4 w0 = *(const float4*)&wvs[h0 + 0];
        const float4 w1 = *(const float4*)&wvs[h0 + 4];
        const float4 w2 = *(const float4*)&wvs[h0 + 8];
        const float4 w3 = *(const float4*)&wvs[h0 + 12];
        #pragma unroll
        for (int qi = 0; qi < 8; qi++) {
            const float* __restrict__ qrow = qs + (qb + qi) * 128 + h0;
            const float4 q0v = *(const float4*)&qrow[0];
            const float4 q1v = *(const float4*)&qrow[4];
            const float4 q2v = *(const float4*)&qrow[8];
            const float4 q3v = *(const float4*)&qrow[12];
            float a = acc[qi];
            a = fmaf(w0.x, tanh_fast(q0v.x + kv0.x), a);
            a = fmaf(w0.y, tanh_fast(q0v.y + kv0.y), a);
            a = fmaf(w0.z, tanh_fast(q0v.z + kv0.z), a);
            a = fmaf(w0.w, tanh_fast(q0v.w + kv0.w), a);
            a = fmaf(w1.x, tanh_fast(q1v.x + kv1.x), a);
            a = fmaf(w1.y, tanh_fast(q1v.y + kv1.y), a);
            a = fmaf(w1.z, tanh_fast(q1v.z + kv1.z), a);
            a = fmaf(w1.w, tanh_fast(q1v.w + kv1.w), a);
            a = fmaf(w2.x, tanh_fast(q2v.x + kv2.x), a);
            a = fmaf(w2.y, tanh_fast(q2v.y + kv2.y), a);
            a = fmaf(w2.z, tanh_fast(q2v.z + kv2.z), a);
            a = fmaf(w2.w, tanh_fast(q2v.w + kv2.w), a);
            a = fmaf(w3.x, tanh_fast(q3v.x + kv3.x), a);
            a = fmaf(w3.y, tanh_fast(q3v.y + kv3.y), a);
            a = fmaf(w3.z, tanh_fast(q3v.z + kv3.z), a);
            a = fmaf(w3.w, tanh_fast(q3v.w + kv3.w), a);
            acc[qi] = a;
        }
    }

    const bool live = (kg < valid);
    #pragma unroll
    for (int qi = 0; qi < 8; qi++) {
        const float p = live ? __expf(acc[qi] - Bsh) : 0.f;
        d_scores[(b * Qn + q0 + qb + qi) * Kn + kg] = p;
    }
}

// ---------------------------------------------------------------------------
// Kernel 3: AV GEMM + inline normalize.  v3:
// Tile 16q x 64v, BK=64, 128 threads, 2q x 4v microtile (8 outputs/thread).
// grid = 4b x 16qt x 4vt = 256.  Double-buffered smem, one sync per phase.
// Thread: tx = tid&15 (v group), ty = tid>>4 (0..7) -> q rows 2ty, 2ty+1.
// ---------------------------------------------------------------------------
__global__ __launch_bounds__(128) void av_gemm(const float* __restrict__ values,
                                               const int* __restrict__ valid_lens,
                                               float* __restrict__ out) {
    const int blk = blockIdx.x;
    const int b  = blk >> 6;
    const int qt = (blk >> 2) & 15;
    const int vt = blk & 3;
    const int q0 = qt * 16, v0 = vt * 64;
    const int kmax = (valid_lens[b] + 63) & ~63;
    const int nPh = kmax >> 6;

    __shared__ float As[2][16][68];   // [buf][q][kk]
    __shared__ float Bs[2][64][68];   // [buf][kk][v]

    const int tid = threadIdx.x;
    const int tx = tid & 15, ty = tid >> 4;     // tx: v/4, ty: 0..7

    // Load mapping (128 threads):
    //  As: 2 float4/thread: rows ty, ty+8; cols tx*4 within phase
    //  Bs: 8 float4/thread: kk = ty + 8i; cols tx*4
    const float* __restrict__ a0p = d_scores + (b * Qn + q0 + ty)     * Kn + tx * 4;
    const float* __restrict__ a1p = d_scores + (b * Qn + q0 + ty + 8) * Kn + tx * 4;
    const float* __restrict__ vbase = values + ((size_t)b * Kn + ty) * Vn + v0 + tx * 4;

    float4 pa[2], pb[8];
    pa[0] = *(const float4*)&a0p[0];
    pa[1] = *(const float4*)&a1p[0];
    #pragma unroll
    for (int i = 0; i < 8; i++)
        pb[i] = *(const float4*)&vbase[(size_t)(8 * i) * Vn];

    // commit phase 0
    *(float4*)&As[0][ty][tx * 4]     = pa[0];
    *(float4*)&As[0][ty + 8][tx * 4] = pa[1];
    #pragma unroll
    for (int i = 0; i < 8; i++)
        *(float4*)&Bs[0][ty + 8 * i][tx * 4] = pb[i];
    __syncthreads();

    float4 acc0 = make_float4(0.f, 0.f, 0.f, 0.f);
    float4 acc1 = make_float4(0.f, 0.f, 0.f, 0.f);
    float sum0 = 0.f, sum1 = 0.f;

    for (int ph = 0; ph < nPh; ph++) {
        const int buf = ph & 1;
        // prefetch next phase into registers (overlaps with compute)
        if (ph + 1 < nPh) {
            const int k0n = (ph + 1) * 64;
            pa[0] = *(const float4*)&a0p[k0n];
            pa[1] = *(const float4*)&a1p[k0n];
            #pragma unroll
            for (int i = 0; i < 8; i++)
                pb[i] = *(const float4*)&vbase[(size_t)(k0n + 8 * i) * Vn];
        }

        #pragma unroll
        for (int kk4 = 0; kk4 < 16; kk4++) {
            const float4 a0 = *(const float4*)&As[buf][2 * ty + 0][kk4 * 4];
            const float4 a1 = *(const float4*)&As[buf][2 * ty + 1][kk4 * 4];
            sum0 += (a0.x + a0.y) + (a0.z + a0.w);
            sum1 += (a1.x + a1.y) + (a1.z + a1.w);
            {
                const float4 bv = *(const float4*)&Bs[buf][kk4 * 4 + 0][tx * 4];
                acc0.x = fmaf(a0.x, bv.x, acc0.x); acc0.y = fmaf(a0.x, bv.y, acc0.y);
                acc0.z = fmaf(a0.x, bv.z, acc0.z); acc0.w = fmaf(a0.x, bv.w, acc0.w);
                acc1.x = fmaf(a1.x, bv.x, acc1.x); acc1.y = fmaf(a1.x, bv.y, acc1.y);
                acc1.z = fmaf(a1.x, bv.z, acc1.z); acc1.w = fmaf(a1.x, bv.w, acc1.w);
            }
            {
                const float4 bv = *(const float4*)&Bs[buf][kk4 * 4 + 1][tx * 4];
                acc0.x = fmaf(a0.y, bv.x, acc0.x); acc0.y = fmaf(a0.y, bv.y, acc0.y);
                acc0.z = fmaf(a0.y, bv.z, acc0.z); acc0.w = fmaf(a0.y, bv.w, acc0.w);
                acc1.x = fmaf(a1.y, bv.x, acc1.x); acc1.y = fmaf(a1.y, bv.y, acc1.y);
                acc1.z = fmaf(a1.y, bv.z, acc1.z); acc1.w = fmaf(a1.y, bv.w, acc1.w);
            }
            {
                const float4 bv = *(const float4*)&Bs[buf][kk4 * 4 + 2][tx * 4];
                acc0.x = fmaf(a0.z, bv.x, acc0.x); acc0.y = fmaf(a0.z, bv.y, acc0.y);
                acc0.z = fmaf(a0.z, bv.z, acc0.z); acc0.w = fmaf(a0.z, bv.w, acc0.w);
                acc1.x = fmaf(a1.z, bv.x, acc1.x); acc1.y = fmaf(a1.z, bv.y, acc1.y);
                acc1.z = fmaf(a1.z, bv.z, acc1.z); acc1.w = fmaf(a1.z, bv.w, acc1.w);
            }
            {
                const float4 bv = *(const float4*)&Bs[buf][kk4 * 4 + 3][tx * 4];
                acc0.x = fmaf(a0.w, bv.x, acc0.x); acc0.y = fmaf(a0.w, bv.y, acc0.y);
                acc0.z = fmaf(a0.w, bv.z, acc0.z); acc0.w = fmaf(a0.w, bv.w, acc0.w);
                acc1.x = fmaf(a1.w, bv.x, acc1.x); acc1.y = fmaf(a1.w, bv.y, acc1.y);
                acc1.z = fmaf(a1.w, bv.z, acc1.z); acc1.w = fmaf(a1.w, bv.w, acc1.w);
            }
        }

        // commit prefetched registers into the other buffer
        if (ph + 1 < nPh) {
            const int nb = buf ^ 1;
            *(float4*)&As[nb][ty][tx * 4]     = pa[0];
            *(float4*)&As[nb][ty + 8][tx * 4] = pa[1];
            #pragma unroll
            for (int i = 0; i < 8; i++)
                *(float4*)&Bs[nb][ty + 8 * i][tx * 4] = pb[i];
        }
        __syncthreads();
    }

    const float inv0 = 1.0f / sum0;
    const float inv1 = 1.0f / sum1;
    float4 o0 = make_float4(acc0.x * inv0, acc0.y * inv0, acc0.z * inv0, acc0.w * inv0);
    float4 o1 = make_float4(acc1.x * inv1, acc1.y * inv1, acc1.z * inv1, acc1.w * inv1);
    *(float4*)&out[((size_t)b * Qn + q0 + 2 * ty + 0) * Vn + v0 + tx * 4] = o0;
    *(float4*)&out[((size_t)b * Qn + q0 + 2 * ty + 1) * Vn + v0 + tx * 4] = o1;
}

extern "C" void kernel_launch(void* const* d_in, const int* in_sizes, int n_in,
                              void* d_out, int out_size) {
    const float* queries    = (const float*)d_in[0];
    const float* keys       = (const float*)d_in[1];
    const float* values     = (const float*)d_in[2];
    const int*   valid_lens = (const int*)  d_in[3];
    const float* W_q        = (const float*)d_in[4];
    const float* W_k        = (const float*)d_in[5];
    const float* w_v        = (const float*)d_in[6];
    float* out              = (float*)d_out;

    transpose_w<<<65, 256>>>(W_q, W_k, w_v);
    proj_gemm<<<320, 256>>>(queries, keys);
    score_kernel<<<512, 256>>>(valid_lens, w_v);
    av_gemm<<<256, 128>>>(values, valid_lens, out);
}